// round 2
// baseline (speedup 1.0000x reference)
#include <cuda_runtime.h>
#include <cuda_bf16.h>
#include <cstdint>

// BCE-with-logits mean over 8192x8192, single kernel.
// Per-block partials + last-block-done final reduction (deterministic:
// fixed block count, no float atomics; int counter self-resets to 0).

#define NBLOCKS   1184   // 148 SMs * 8 CTAs
#define NTHREADS  256

__device__ float g_partials[NBLOCKS];
__device__ unsigned int g_count = 0;   // always 0 at kernel entry

__device__ __forceinline__ float block_reduce(float acc, float* warp_sums)
{
    #pragma unroll
    for (int off = 16; off > 0; off >>= 1)
        acc += __shfl_down_sync(0xFFFFFFFFu, acc, off);
    int lane = threadIdx.x & 31;
    int wid  = threadIdx.x >> 5;
    if (lane == 0) warp_sums[wid] = acc;
    __syncthreads();
    float v = 0.0f;
    if (wid == 0) {
        v = (lane < NTHREADS / 32) ? warp_sums[lane] : 0.0f;
        #pragma unroll
        for (int off = 16; off > 0; off >>= 1)
            v += __shfl_down_sync(0xFFFFFFFFu, v, off);
    }
    return v;   // valid in warp 0 lane 0
}

__device__ __forceinline__ float bce4(float4 xv, int4 tv)
{
    float y0 = tv.x ? -xv.x : xv.x;
    float y1 = tv.y ? -xv.y : xv.y;
    float y2 = tv.z ? -xv.z : xv.z;
    float y3 = tv.w ? -xv.w : xv.w;
    float s0 = fmaxf(y0, 0.0f) + __logf(1.0f + __expf(-fabsf(y0)));
    float s1 = fmaxf(y1, 0.0f) + __logf(1.0f + __expf(-fabsf(y1)));
    float s2 = fmaxf(y2, 0.0f) + __logf(1.0f + __expf(-fabsf(y2)));
    float s3 = fmaxf(y3, 0.0f) + __logf(1.0f + __expf(-fabsf(y3)));
    return (s0 + s1) + (s2 + s3);
}

__global__ __launch_bounds__(NTHREADS) void bce_fused_kernel(
    const float* __restrict__ x, const int* __restrict__ t,
    float* __restrict__ out, long long n4, float inv_n)
{
    const float4* __restrict__ x4 = (const float4*)x;
    const int4*   __restrict__ t4 = (const int4*)t;

    const long long stride = (long long)gridDim.x * blockDim.x;
    long long i = (long long)blockIdx.x * blockDim.x + threadIdx.x;

    float acc = 0.0f;
    // unrolled x2: two independent load pairs in flight per iteration
    for (; i + stride < n4; i += 2 * stride) {
        float4 xa = x4[i];
        int4   ta = t4[i];
        float4 xb = x4[i + stride];
        int4   tb = t4[i + stride];
        acc += bce4(xa, ta);
        acc += bce4(xb, tb);
    }
    if (i < n4)
        acc += bce4(x4[i], t4[i]);

    __shared__ float warp_sums[NTHREADS / 32];
    float bsum = block_reduce(acc, warp_sums);

    __shared__ bool is_last;
    if (threadIdx.x == 0) {
        g_partials[blockIdx.x] = bsum;
        __threadfence();
        unsigned int done = atomicAdd(&g_count, 1u);
        is_last = (done == (unsigned int)(gridDim.x - 1));
    }
    __syncthreads();

    if (is_last) {
        float a2 = 0.0f;
        for (int k = threadIdx.x; k < NBLOCKS; k += NTHREADS)
            a2 += g_partials[k];
        __syncthreads();   // reuse warp_sums safely
        float total = block_reduce(a2, warp_sums);
        if (threadIdx.x == 0) {
            out[0] = total * inv_n;
            g_count = 0;   // reset for next (graph-replayed) launch
        }
    }
}

extern "C" void kernel_launch(void* const* d_in, const int* in_sizes, int n_in,
                              void* d_out, int out_size)
{
    const float* x = (const float*)d_in[0];
    const int*   t = (const int*)d_in[1];
    float* out = (float*)d_out;

    long long n  = (long long)in_sizes[0];   // 64M, divisible by 4
    long long n4 = n >> 2;

    bce_fused_kernel<<<NBLOCKS, NTHREADS>>>(x, t, out, n4, 1.0f / (float)n);
}

// round 3
// speedup vs baseline: 1.0970x; 1.0970x over previous
#include <cuda_runtime.h>
#include <cuda_bf16.h>
#include <cstdint>

// BCE-with-logits mean over 8192x8192, single kernel.
// Simple grid-stride loop (low MLP_p1 -> low cross-CTA spread),
// streaming loads (__ldcs), last-block-done final reduction.

#define NBLOCKS   1184   // 148 SMs * 8 CTAs
#define NTHREADS  256

__device__ float g_partials[NBLOCKS];
__device__ unsigned int g_count = 0;   // always 0 at kernel entry

__device__ __forceinline__ float block_reduce(float acc, float* warp_sums)
{
    #pragma unroll
    for (int off = 16; off > 0; off >>= 1)
        acc += __shfl_down_sync(0xFFFFFFFFu, acc, off);
    int lane = threadIdx.x & 31;
    int wid  = threadIdx.x >> 5;
    if (lane == 0) warp_sums[wid] = acc;
    __syncthreads();
    float v = 0.0f;
    if (wid == 0) {
        v = (lane < NTHREADS / 32) ? warp_sums[lane] : 0.0f;
        #pragma unroll
        for (int off = 16; off > 0; off >>= 1)
            v += __shfl_down_sync(0xFFFFFFFFu, v, off);
    }
    return v;   // valid in warp 0 lane 0
}

__device__ __forceinline__ float bce4(float4 xv, int4 tv)
{
    float y0 = tv.x ? -xv.x : xv.x;
    float y1 = tv.y ? -xv.y : xv.y;
    float y2 = tv.z ? -xv.z : xv.z;
    float y3 = tv.w ? -xv.w : xv.w;
    float s0 = fmaxf(y0, 0.0f) + __logf(1.0f + __expf(-fabsf(y0)));
    float s1 = fmaxf(y1, 0.0f) + __logf(1.0f + __expf(-fabsf(y1)));
    float s2 = fmaxf(y2, 0.0f) + __logf(1.0f + __expf(-fabsf(y2)));
    float s3 = fmaxf(y3, 0.0f) + __logf(1.0f + __expf(-fabsf(y3)));
    return (s0 + s1) + (s2 + s3);
}

__global__ __launch_bounds__(NTHREADS) void bce_fused_kernel(
    const float* __restrict__ x, const int* __restrict__ t,
    float* __restrict__ out, long long n4, float inv_n)
{
    const float4* __restrict__ x4 = (const float4*)x;
    const int4*   __restrict__ t4 = (const int4*)t;

    const long long stride = (long long)gridDim.x * blockDim.x;

    float acc = 0.0f;
    for (long long i = (long long)blockIdx.x * blockDim.x + threadIdx.x;
         i < n4; i += stride) {
        float4 xv = __ldcs(&x4[i]);   // evict-first: zero-reuse stream
        int4   tv = __ldcs(&t4[i]);
        acc += bce4(xv, tv);
    }

    __shared__ float warp_sums[NTHREADS / 32];
    float bsum = block_reduce(acc, warp_sums);

    __shared__ bool is_last;
    if (threadIdx.x == 0) {
        g_partials[blockIdx.x] = bsum;
        __threadfence();
        unsigned int done = atomicAdd(&g_count, 1u);
        is_last = (done == (unsigned int)(gridDim.x - 1));
    }
    __syncthreads();

    if (is_last) {
        float a2 = 0.0f;
        for (int k = threadIdx.x; k < NBLOCKS; k += NTHREADS)
            a2 += g_partials[k];
        __syncthreads();   // warp_sums reuse is safe after this
        float total = block_reduce(a2, warp_sums);
        if (threadIdx.x == 0) {
            out[0] = total * inv_n;
            g_count = 0;   // reset for next graph replay
        }
    }
}

extern "C" void kernel_launch(void* const* d_in, const int* in_sizes, int n_in,
                              void* d_out, int out_size)
{
    const float* x = (const float*)d_in[0];
    const int*   t = (const int*)d_in[1];
    float* out = (float*)d_out;

    long long n  = (long long)in_sizes[0];   // 64M, divisible by 4
    long long n4 = n >> 2;

    bce_fused_kernel<<<NBLOCKS, NTHREADS>>>(x, t, out, n4, 1.0f / (float)n);
}

// round 4
// speedup vs baseline: 1.1210x; 1.0218x over previous
#include <cuda_runtime.h>
#include <cuda_bf16.h>
#include <cstdint>

// BCE-with-logits mean over 8192x8192, single kernel.
// Dynamic chunk scheduling (atomic work counter, prefetched grab) to kill
// the ~10% between-SM spread floor of static partitioning.
// Last-block-done final reduction; counters self-reset for graph replay.

#define NBLOCKS   1184          // 148 SMs * 8 CTAs (one full wave)
#define NTHREADS  256
#define CHUNK_IT  2
#define CHUNK     (NTHREADS * CHUNK_IT)   // 512 float4 per chunk

__device__ float g_partials[NBLOCKS];
__device__ unsigned int g_count = 0;    // always 0 at kernel entry
__device__ unsigned int g_work  = 0;    // always 0 at kernel entry

__device__ __forceinline__ float block_reduce(float acc, float* warp_sums)
{
    #pragma unroll
    for (int off = 16; off > 0; off >>= 1)
        acc += __shfl_down_sync(0xFFFFFFFFu, acc, off);
    int lane = threadIdx.x & 31;
    int wid  = threadIdx.x >> 5;
    if (lane == 0) warp_sums[wid] = acc;
    __syncthreads();
    float v = 0.0f;
    if (wid == 0) {
        v = (lane < NTHREADS / 32) ? warp_sums[lane] : 0.0f;
        #pragma unroll
        for (int off = 16; off > 0; off >>= 1)
            v += __shfl_down_sync(0xFFFFFFFFu, v, off);
    }
    return v;   // valid in warp 0 lane 0
}

__device__ __forceinline__ float bce1(float x, int t)
{
    // t in {0,1}: flip sign of x when t==1  (y = t ? -x : x)
    float y = __int_as_float(__float_as_int(x) ^ (t << 31));
    return fmaxf(y, 0.0f) + __logf(1.0f + __expf(-fabsf(y)));
}

__device__ __forceinline__ float bce4(float4 xv, int4 tv)
{
    float s0 = bce1(xv.x, tv.x);
    float s1 = bce1(xv.y, tv.y);
    float s2 = bce1(xv.z, tv.z);
    float s3 = bce1(xv.w, tv.w);
    return (s0 + s1) + (s2 + s3);
}

__global__ __launch_bounds__(NTHREADS) void bce_dyn_kernel(
    const float* __restrict__ x, const int* __restrict__ t,
    float* __restrict__ out, long long n4, float inv_n, int nchunks)
{
    const float4* __restrict__ x4 = (const float4*)x;
    const int4*   __restrict__ t4 = (const int4*)t;

    __shared__ int   s_chunk;
    __shared__ float warp_sums[NTHREADS / 32];

    float acc = 0.0f;

    if (threadIdx.x == 0) s_chunk = (int)atomicAdd(&g_work, 1u);
    __syncthreads();
    int chunk = s_chunk;
    __syncthreads();

    while (chunk < nchunks) {
        // prefetch next chunk index; result consumed ~chunk-time later
        if (threadIdx.x == 0) s_chunk = (int)atomicAdd(&g_work, 1u);

        long long base = (long long)chunk * CHUNK;
        #pragma unroll 1
        for (int j = 0; j < CHUNK_IT; j++) {
            long long i = base + j * NTHREADS + threadIdx.x;
            if (i < n4) {
                float4 xv = __ldcs(&x4[i]);
                int4   tv = __ldcs(&t4[i]);
                acc += bce4(xv, tv);
            }
        }

        __syncthreads();          // s_chunk write visible to all
        chunk = s_chunk;
        __syncthreads();          // all read before next overwrite
    }

    float bsum = block_reduce(acc, warp_sums);

    __shared__ bool is_last;
    if (threadIdx.x == 0) {
        g_partials[blockIdx.x] = bsum;
        __threadfence();
        unsigned int done = atomicAdd(&g_count, 1u);
        is_last = (done == (unsigned int)(gridDim.x - 1));
    }
    __syncthreads();

    if (is_last) {
        float a2 = 0.0f;
        for (int k = threadIdx.x; k < NBLOCKS; k += NTHREADS)
            a2 += g_partials[k];
        __syncthreads();
        float total = block_reduce(a2, warp_sums);
        if (threadIdx.x == 0) {
            out[0] = total * inv_n;
            g_count = 0;          // reset for next graph replay
            g_work  = 0;
        }
    }
}

extern "C" void kernel_launch(void* const* d_in, const int* in_sizes, int n_in,
                              void* d_out, int out_size)
{
    const float* x = (const float*)d_in[0];
    const int*   t = (const int*)d_in[1];
    float* out = (float*)d_out;

    long long n  = (long long)in_sizes[0];   // 64M
    long long n4 = n >> 2;
    int nchunks  = (int)((n4 + CHUNK - 1) / CHUNK);

    bce_dyn_kernel<<<NBLOCKS, NTHREADS>>>(x, t, out, n4, 1.0f / (float)n, nchunks);
}